// round 13
// baseline (speedup 1.0000x reference)
#include <cuda_runtime.h>

#define SEQ   8192
#define HD    1024
#define G4    4096
#define NIN   64
#define NLAYER 5
#define NCTA  128

// ---------------- scratch (device globals; no allocation allowed) ------------
__device__ float    g_bufA[(size_t)SEQ * HD];   // activation ping
__device__ float    g_bufB[(size_t)SEQ * HD];   // activation pong
__device__ float    g_Z[(size_t)SEQ * G4];      // input projections (with bias)
__device__ float    g_h[2 * HD];                // double-buffered hidden state
__device__ unsigned g_flags[NCTA];              // per-CTA monotonic step flags (packed)

// ---------------- math helpers ----------------------------------------------
__device__ __forceinline__ float sigmf(float x) { return 1.0f / (1.0f + __expf(-x)); }
__device__ __forceinline__ float tanh_fast(float x) { return 1.0f - 2.0f / (__expf(2.0f * x) + 1.0f); }

__device__ __forceinline__ unsigned ld_acq(const unsigned* p) {
    unsigned v;
    asm volatile("ld.acquire.gpu.global.b32 %0, [%1];" : "=r"(v) : "l"(p) : "memory");
    return v;
}
__device__ __forceinline__ void st_relx(unsigned* p, unsigned v) {
    asm volatile("st.relaxed.gpu.global.b32 [%0], %1;" :: "l"(p), "r"(v) : "memory");
}
__device__ __forceinline__ void sts_rel_cta(unsigned addr, unsigned v) {
    asm volatile("st.release.cta.shared.b32 [%0], %1;" :: "r"(addr), "r"(v) : "memory");
}
__device__ __forceinline__ unsigned lds_acq_cta(unsigned addr) {
    unsigned v;
    asm volatile("ld.acquire.cta.shared.b32 %0, [%1];" : "=r"(v) : "r"(addr) : "memory");
    return v;
}

// ---------------- init: flags = 0, seed layer-0 h_{-1} -----------------------
__global__ void k_init(const float* __restrict__ h0l) {
    const int i = threadIdx.x + blockIdx.x * blockDim.x;   // 0..1023
    if (i < NCTA) g_flags[i] = 0u;
    g_h[HD + i] = h0l[i];    // t=0 reads buf[1]
}

// ---------------- prep (layers >= 1): seed h_{-1} = h0[layer] ----------------
__global__ void k_prep(const float* __restrict__ h0l) {
    const int i = threadIdx.x + blockIdx.x * blockDim.x;
    if (i < HD) g_h[HD + i] = h0l[i];
}

// ---------------- first layer: leaky_relu(x @ w1^T + b1) ---------------------
__global__ __launch_bounds__(256) void k_first(const float* __restrict__ x,
                                               const float* __restrict__ w1,
                                               const float* __restrict__ b1,
                                               float* __restrict__ out) {
    __shared__ float xs[64][NIN];
    __shared__ float ws[64][NIN + 1];
    const int t0 = blockIdx.x * 64;
    const int h0 = blockIdx.y * 64;
    const int tid = threadIdx.x;

    for (int i = tid; i < 64 * NIN; i += 256)
        xs[i >> 6][i & 63] = x[(size_t)(t0 + (i >> 6)) * NIN + (i & 63)];
    for (int i = tid; i < 64 * NIN; i += 256)
        ws[i >> 6][i & 63] = w1[(size_t)(h0 + (i >> 6)) * NIN + (i & 63)];
    __syncthreads();

    const int h = tid & 63, tq = tid >> 6;
    float acc[16];
#pragma unroll
    for (int i = 0; i < 16; i++) acc[i] = 0.0f;

#pragma unroll 16
    for (int k = 0; k < NIN; k++) {
        const float wv = ws[h][k];
#pragma unroll
        for (int i = 0; i < 16; i++) acc[i] = fmaf(xs[tq * 16 + i][k], wv, acc[i]);
    }
    const float bb = b1[h0 + h];
#pragma unroll
    for (int i = 0; i < 16; i++) {
        float v = acc[i] + bb;
        v = (v >= 0.0f) ? v : 0.01f * v;
        out[(size_t)(t0 + tq * 16 + i) * HD + h0 + h] = v;
    }
}

// ---------------- input-projection GEMM: Z = X @ Wih^T + (b_ih + b_hh) -------
// R2-exact: 128x128x8 SGEMM, 256 threads, 8x8 accumulators, register prefetch.
__global__ __launch_bounds__(256, 2) void k_gemm(const float* __restrict__ A,   // (SEQ, HD)
                                                 const float* __restrict__ W,   // (G4, HD)
                                                 const float* __restrict__ bi,
                                                 const float* __restrict__ bh) {
    __shared__ float As[8][128];
    __shared__ float Bs[8][128];
    const int tid = threadIdx.x;
    const int tx = tid & 15, ty = tid >> 4;
    const int m0 = blockIdx.y * 128, n0 = blockIdx.x * 128;
    const int lr = tid >> 1, lk = (tid & 1) * 4;

    const float* Ap = A + (size_t)(m0 + lr) * HD + lk;
    const float* Wp = W + (size_t)(n0 + lr) * HD + lk;

    float acc[8][8];
#pragma unroll
    for (int i = 0; i < 8; i++)
#pragma unroll
        for (int j = 0; j < 8; j++) acc[i][j] = 0.0f;

    float4 av = *(const float4*)(Ap);
    float4 bv = *(const float4*)(Wp);

    for (int k0 = 0; k0 < HD; k0 += 8) {
        __syncthreads();
        As[lk + 0][lr] = av.x; As[lk + 1][lr] = av.y; As[lk + 2][lr] = av.z; As[lk + 3][lr] = av.w;
        Bs[lk + 0][lr] = bv.x; Bs[lk + 1][lr] = bv.y; Bs[lk + 2][lr] = bv.z; Bs[lk + 3][lr] = bv.w;
        __syncthreads();
        if (k0 + 8 < HD) {
            av = *(const float4*)(Ap + k0 + 8);
            bv = *(const float4*)(Wp + k0 + 8);
        }
#pragma unroll
        for (int kk = 0; kk < 8; kk++) {
            float ar[8], br[8];
            *(float4*)(ar)     = *(const float4*)&As[kk][ty * 8];
            *(float4*)(ar + 4) = *(const float4*)&As[kk][ty * 8 + 4];
            *(float4*)(br)     = *(const float4*)&Bs[kk][tx * 8];
            *(float4*)(br + 4) = *(const float4*)&Bs[kk][tx * 8 + 4];
#pragma unroll
            for (int i = 0; i < 8; i++)
#pragma unroll
                for (int j = 0; j < 8; j++) acc[i][j] = fmaf(ar[i], br[j], acc[i][j]);
        }
    }
    float bb[8];
#pragma unroll
    for (int j = 0; j < 8; j++) bb[j] = bi[n0 + tx * 8 + j] + bh[n0 + tx * 8 + j];
#pragma unroll
    for (int i = 0; i < 8; i++) {
        const size_t m = (size_t)(m0 + ty * 8 + i);
        float4 o0, o1;
        o0.x = acc[i][0] + bb[0]; o0.y = acc[i][1] + bb[1];
        o0.z = acc[i][2] + bb[2]; o0.w = acc[i][3] + bb[3];
        o1.x = acc[i][4] + bb[4]; o1.y = acc[i][5] + bb[5];
        o1.z = acc[i][6] + bb[6]; o1.w = acc[i][7] + bb[7];
        *(float4*)&g_Z[m * G4 + n0 + tx * 8]     = o0;
        *(float4*)&g_Z[m * G4 + n0 + tx * 8 + 4] = o1;
    }
}

// ---------------- recurrent persistent kernel --------------------------------
// R2-exact except the flag DETECT is hierarchical: warp 0 polls all 128 packed
// flags (4 sector-strided ld.acquire.gpu per lane, ~8x less L2 flag traffic
// than 8 polling warps), then releases warps 1-7 via an SMEM go-word
// (st.release.cta / ld.acquire.cta spin -- LDS only, no L2).
__global__ __launch_bounds__(256, 1) void k_rec(const float* __restrict__ Whh,  // (G4, HD)
                                                const float* __restrict__ c0l,  // (HD)
                                                const float* __restrict__ Zin,  // (SEQ, G4)
                                                float* __restrict__ Xout,       // (SEQ, HD)
                                                unsigned base) {
    __shared__ float sh[2][HD];
    __shared__ unsigned sh_go;
    const int tid = threadIdx.x;
    const int w = tid >> 5, lane = tid & 31;
    const int u = blockIdx.x * 8 + w;

    unsigned sb, go_addr;
    asm("{ .reg .u64 t; cvta.to.shared.u64 t, %1; cvt.u32.u64 %0, t; }"
        : "=r"(sb) : "l"((void*)sh));
    asm("{ .reg .u64 t; cvta.to.shared.u64 t, %1; cvt.u32.u64 %0, t; }"
        : "=r"(go_addr) : "l"((void*)&sh_go));
    sb += (unsigned)lane * 8u;

    if (tid == 0) sh_go = 0u;

    // packed weight pairs: lane owns k in {64j+2*lane, 64j+2*lane+1}
    unsigned long long wp[4][16];
#pragma unroll
    for (int g = 0; g < 4; g++) {
        const float* rp = Whh + (size_t)(g * HD + u) * HD + 2 * lane;
#pragma unroll
        for (int j = 0; j < 16; j++) {
            const float2 v = *(const float2*)(rp + 64 * j);
            asm("mov.b64 %0, {%1, %2};" : "=l"(wp[g][j]) : "f"(v.x), "f"(v.y));
        }
    }
    float c = c0l[u];   // only lane 0's copy is used
    __syncthreads();    // sh_go init visible to all warps

#pragma unroll 1
    for (int t = 0; t < SEQ; t++) {
        // z prefetch (lane0 of each warp), issued before the wait (R2-exact)
        float z0 = 0.f, z1 = 0.f, z2 = 0.f, z3 = 0.f;
        if (lane == 0) {
            const float* zp = Zin + (size_t)t * G4 + u;
            z0 = zp[0]; z1 = zp[HD]; z2 = zp[2 * HD]; z3 = zp[3 * HD];
        }

        const unsigned target = base + (unsigned)t;
        // ---- hierarchical detect ----
        if (w == 0) {
            // warp 0: lane li polls flags {li, li+32, li+64, li+96}
            for (;;) {
                const unsigned f0 = ld_acq(&g_flags[lane]);
                const unsigned f1 = ld_acq(&g_flags[lane + 32]);
                const unsigned f2 = ld_acq(&g_flags[lane + 64]);
                const unsigned f3 = ld_acq(&g_flags[lane + 96]);
                const bool ok = (f0 >= target) & (f1 >= target) &
                                (f2 >= target) & (f3 >= target);
                if (__all_sync(0xffffffffu, ok)) break;
            }
            if (lane == 0) sts_rel_cta(go_addr, target + 1u);   // release warps 1-7
        } else {
            while (lds_acq_cta(go_addr) < target + 1u) {}       // LDS spin, no L2
        }
        // stage h_{t-1} into SMEM
        {
            const float4 v = __ldcg((const float4*)(g_h + ((t + 1) & 1) * HD) + tid);
            *(float4*)&sh[t & 1][tid * 4] = v;
        }
        __syncthreads();

        // packed dot: 64 x fma.rn.f32x2 + 16 x LDS.64 (R2-exact)
        const unsigned sbase = sb + (unsigned)((t & 1) << 12);
        unsigned long long a0 = 0ull, a1 = 0ull, a2 = 0ull, a3 = 0ull;
#pragma unroll
        for (int j = 0; j < 16; j++) {
            unsigned long long hp;
            asm volatile("ld.shared.b64 %0, [%1];" : "=l"(hp) : "r"(sbase + (unsigned)(j * 256)));
            asm("fma.rn.f32x2 %0, %1, %2, %0;" : "+l"(a0) : "l"(wp[0][j]), "l"(hp));
            asm("fma.rn.f32x2 %0, %1, %2, %0;" : "+l"(a1) : "l"(wp[1][j]), "l"(hp));
            asm("fma.rn.f32x2 %0, %1, %2, %0;" : "+l"(a2) : "l"(wp[2][j]), "l"(hp));
            asm("fma.rn.f32x2 %0, %1, %2, %0;" : "+l"(a3) : "l"(wp[3][j]), "l"(hp));
        }
        float s0, s1, s2, s3;
        {
            float x, y;
            asm("mov.b64 {%0,%1}, %2;" : "=f"(x), "=f"(y) : "l"(a0)); s0 = x + y;
            asm("mov.b64 {%0,%1}, %2;" : "=f"(x), "=f"(y) : "l"(a1)); s1 = x + y;
            asm("mov.b64 {%0,%1}, %2;" : "=f"(x), "=f"(y) : "l"(a2)); s2 = x + y;
            asm("mov.b64 {%0,%1}, %2;" : "=f"(x), "=f"(y) : "l"(a3)); s3 = x + y;
        }
#pragma unroll
        for (int off = 16; off; off >>= 1) {
            s0 += __shfl_xor_sync(0xffffffffu, s0, off);
            s1 += __shfl_xor_sync(0xffffffffu, s1, off);
            s2 += __shfl_xor_sync(0xffffffffu, s2, off);
            s3 += __shfl_xor_sync(0xffffffffu, s3, off);
        }
        float h = 0.f;
        if (lane == 0) {
            const float ig = sigmf(s0 + z0);
            const float fg = sigmf(s1 + z1);
            const float gg = tanh_fast(s2 + z2);
            const float og = sigmf(s3 + z3);
            c = fg * c + ig * gg;
            h = og * tanh_fast(c);
            __stcg(&g_h[(t & 1) * HD + u], h);      // broadcast buffer (L2)
        }
        __syncthreads();                            // all h stores precede fence
        if (tid == 0) {
            __threadfence();                        // publish h (cumulative)
            st_relx(&g_flags[blockIdx.x], target + 1u);
        }
        if (lane == 0)
            Xout[(size_t)t * HD + u] = h;           // off the critical path
    }
}

// ---------------- final: tanh(leaky_relu(X) @ w2^T + b2) ---------------------
__global__ __launch_bounds__(256) void k_final(const float* __restrict__ Xin,
                                               const float* __restrict__ w2,   // (NIN, HD)
                                               const float* __restrict__ b2,
                                               float* __restrict__ y) {
    __shared__ float xs[64][65];
    __shared__ float ws[64][65];
    const int t0 = blockIdx.x * 64;
    const int tid = threadIdx.x;
    const int o = tid & 63, tq = tid >> 6;

    float acc[16];
#pragma unroll
    for (int i = 0; i < 16; i++) acc[i] = 0.0f;

    for (int k0 = 0; k0 < HD; k0 += 64) {
        __syncthreads();
        for (int i = tid; i < 64 * 64; i += 256) {
            const int r = i >> 6, cc = i & 63;
            float v = Xin[(size_t)(t0 + r) * HD + k0 + cc];
            xs[r][cc] = (v >= 0.0f) ? v : 0.01f * v;
            ws[r][cc] = w2[(size_t)r * HD + k0 + cc];
        }
        __syncthreads();
#pragma unroll 16
        for (int k = 0; k < 64; k++) {
            const float wv = ws[o][k];
#pragma unroll
            for (int i = 0; i < 16; i++) acc[i] = fmaf(xs[tq * 16 + i][k], wv, acc[i]);
        }
    }
    const float bb = b2[o];
#pragma unroll
    for (int i = 0; i < 16; i++)
        y[(size_t)(t0 + tq * 16 + i) * NIN + o] = tanh_fast(acc[i] + bb);
}

// ---------------- host launcher ----------------------------------------------
extern "C" void kernel_launch(void* const* d_in, const int* in_sizes, int n_in,
                              void* d_out, int out_size) {
    const float* data_in = (const float*)d_in[0];
    const float* w1      = (const float*)d_in[1];
    const float* b1      = (const float*)d_in[2];
    const float* W_ih    = (const float*)d_in[3];
    const float* W_hh    = (const float*)d_in[4];
    const float* b_ih    = (const float*)d_in[5];
    const float* b_hh    = (const float*)d_in[6];
    const float* w2      = (const float*)d_in[7];
    const float* b2      = (const float*)d_in[8];
    const float* h0      = (const float*)d_in[9];
    const float* c0      = (const float*)d_in[10];
    float* out = (float*)d_out;

    static float* dA = nullptr;
    static float* dB = nullptr;
    static float* dZ = nullptr;
    if (!dA) {   // host-side symbol queries; not allocations
        cudaGetSymbolAddress((void**)&dA, g_bufA);
        cudaGetSymbolAddress((void**)&dB, g_bufB);
        cudaGetSymbolAddress((void**)&dZ, g_Z);
    }
    float* bufs[2] = { dA, dB };

    k_init<<<4, 256>>>(h0);                                          // launch 1
    k_first<<<dim3(SEQ / 64, HD / 64), 256>>>(data_in, w1, b1, dA);  // launch 2

    for (int l = 0; l < NLAYER; l++) {
        const float* Xin = bufs[l & 1];
        float* Xout = bufs[(l & 1) ^ 1];
        if (l > 0)
            k_prep<<<4, 256>>>(h0 + (size_t)l * HD);
        k_gemm<<<dim3(G4 / 128, SEQ / 128), 256>>>(Xin,              // launch 3 (l=0)
                                                   W_ih + (size_t)l * G4 * HD,
                                                   b_ih + (size_t)l * G4,
                                                   b_hh + (size_t)l * G4);
        k_rec<<<NCTA, 256>>>(W_hh + (size_t)l * G4 * HD,             // launch 4 (l=0): profiled
                             c0 + (size_t)l * HD,
                             dZ,
                             Xout,
                             (unsigned)(l * SEQ));
    }
    k_final<<<SEQ / 64, 256>>>(bufs[NLAYER & 1], w2, b2, out);
}

// round 14
// speedup vs baseline: 1.3397x; 1.3397x over previous
#include <cuda_runtime.h>
#include <mma.h>

#define SEQ   8192
#define HD    1024
#define G4    4096
#define NIN   64
#define NLAYER 5
#define NCTA  128

using namespace nvcuda;

// ---------------- scratch (device globals; no allocation allowed) ------------
__device__ float    g_bufA[(size_t)SEQ * HD];   // activation ping
__device__ float    g_bufB[(size_t)SEQ * HD];   // activation pong
__device__ float    g_Z[(size_t)SEQ * G4];      // input projections (with bias)
__device__ float    g_h[2 * HD];                // double-buffered hidden state
__device__ unsigned g_flags[NCTA];              // per-CTA monotonic step flags

// ---------------- math helpers ----------------------------------------------
__device__ __forceinline__ float sigmf(float x) { return 1.0f / (1.0f + __expf(-x)); }
__device__ __forceinline__ float tanh_fast(float x) { return 1.0f - 2.0f / (__expf(2.0f * x) + 1.0f); }

__device__ __forceinline__ unsigned ld_acq(const unsigned* p) {
    unsigned v;
    asm volatile("ld.acquire.gpu.global.b32 %0, [%1];" : "=r"(v) : "l"(p) : "memory");
    return v;
}
__device__ __forceinline__ void st_relx(unsigned* p, unsigned v) {
    asm volatile("st.relaxed.gpu.global.b32 [%0], %1;" :: "l"(p), "r"(v) : "memory");
}

// ---------------- init / prep / nop ------------------------------------------
__global__ void k_init(const float* __restrict__ h0l) {
    const int i = threadIdx.x + blockIdx.x * blockDim.x;   // 0..1023
    if (i < NCTA) g_flags[i] = 0u;
    g_h[HD + i] = h0l[i];    // t=0 reads buf[1]
}
__global__ void k_prep(const float* __restrict__ h0l) {
    const int i = threadIdx.x + blockIdx.x * blockDim.x;
    if (i < HD) g_h[HD + i] = h0l[i];
}
__global__ void k_nop() {}

// ---------------- first layer: leaky_relu(x @ w1^T + b1) ---------------------
__global__ __launch_bounds__(256) void k_first(const float* __restrict__ x,
                                               const float* __restrict__ w1,
                                               const float* __restrict__ b1,
                                               float* __restrict__ out) {
    __shared__ float xs[64][NIN];
    __shared__ float ws[64][NIN + 1];
    const int t0 = blockIdx.x * 64;
    const int h0 = blockIdx.y * 64;
    const int tid = threadIdx.x;

    for (int i = tid; i < 64 * NIN; i += 256)
        xs[i >> 6][i & 63] = x[(size_t)(t0 + (i >> 6)) * NIN + (i & 63)];
    for (int i = tid; i < 64 * NIN; i += 256)
        ws[i >> 6][i & 63] = w1[(size_t)(h0 + (i >> 6)) * NIN + (i & 63)];
    __syncthreads();

    const int h = tid & 63, tq = tid >> 6;
    float acc[16];
#pragma unroll
    for (int i = 0; i < 16; i++) acc[i] = 0.0f;

#pragma unroll 16
    for (int k = 0; k < NIN; k++) {
        const float wv = ws[h][k];
#pragma unroll
        for (int i = 0; i < 16; i++) acc[i] = fmaf(xs[tq * 16 + i][k], wv, acc[i]);
    }
    const float bb = b1[h0 + h];
#pragma unroll
    for (int i = 0; i < 16; i++) {
        float v = acc[i] + bb;
        v = (v >= 0.0f) ? v : 0.01f * v;
        out[(size_t)(t0 + tq * 16 + i) * HD + h0 + h] = v;
    }
}

// ---------------- tensor-core GEMM (3xTF32): Z = X @ W^T + (bi + bh) ---------
// 128x128 CTA tile, k-step 8. hi/lo tf32 split in SMEM; 8 warps x (4m x 2n)
// wmma 16x16x8 fragments; 3 mmas per tile-pair (hi*hi, hi*lo, lo*hi) -> ~fp32
// accuracy at tensor-pipe rate (fallback HMMA on sm_103a).
__global__ __launch_bounds__(256, 2) void k_gemm(const float* __restrict__ A,   // (SEQ, HD)
                                                 const float* __restrict__ W,   // (G4, HD)
                                                 const float* __restrict__ bi,
                                                 const float* __restrict__ bh,
                                                 float* __restrict__ Z) {
    __shared__ __align__(16) float As_hi[128][8], As_lo[128][8];
    __shared__ __align__(16) float Bs_hi[128][8], Bs_lo[128][8];
    __shared__ __align__(16) float scr[8][16][24];
    __shared__ float bb[128];

    const int tid = threadIdx.x;
    const int wid = tid >> 5, lane = tid & 31;
    const int m0 = blockIdx.y * 128, n0 = blockIdx.x * 128;
    const int wm = wid & 1, wn = wid >> 1;        // warp tile: m = wm*64+, n = wn*32+
    const int row = tid >> 1, seg = (tid & 1) * 4;

    if (tid < 128) bb[tid] = bi[n0 + tid] + bh[n0 + tid];

    const float* Ap = A + (size_t)(m0 + row) * HD + seg;
    const float* Wp = W + (size_t)(n0 + row) * HD + seg;

    wmma::fragment<wmma::accumulator, 16, 16, 8, float> acc[4][2];
#pragma unroll
    for (int i = 0; i < 4; i++)
#pragma unroll
        for (int j = 0; j < 2; j++) wmma::fill_fragment(acc[i][j], 0.0f);

    float4 av = *(const float4*)(Ap);
    float4 bv = *(const float4*)(Wp);

    for (int k0 = 0; k0 < HD; k0 += 8) {
        __syncthreads();
        {   // hi/lo split -> SMEM
            float hx = wmma::__float_to_tf32(av.x), hy = wmma::__float_to_tf32(av.y);
            float hz = wmma::__float_to_tf32(av.z), hw = wmma::__float_to_tf32(av.w);
            As_hi[row][seg + 0] = hx; As_lo[row][seg + 0] = wmma::__float_to_tf32(av.x - hx);
            As_hi[row][seg + 1] = hy; As_lo[row][seg + 1] = wmma::__float_to_tf32(av.y - hy);
            As_hi[row][seg + 2] = hz; As_lo[row][seg + 2] = wmma::__float_to_tf32(av.z - hz);
            As_hi[row][seg + 3] = hw; As_lo[row][seg + 3] = wmma::__float_to_tf32(av.w - hw);
            hx = wmma::__float_to_tf32(bv.x); hy = wmma::__float_to_tf32(bv.y);
            hz = wmma::__float_to_tf32(bv.z); hw = wmma::__float_to_tf32(bv.w);
            Bs_hi[row][seg + 0] = hx; Bs_lo[row][seg + 0] = wmma::__float_to_tf32(bv.x - hx);
            Bs_hi[row][seg + 1] = hy; Bs_lo[row][seg + 1] = wmma::__float_to_tf32(bv.y - hy);
            Bs_hi[row][seg + 2] = hz; Bs_lo[row][seg + 2] = wmma::__float_to_tf32(bv.z - hz);
            Bs_hi[row][seg + 3] = hw; Bs_lo[row][seg + 3] = wmma::__float_to_tf32(bv.w - hw);
        }
        __syncthreads();
        if (k0 + 8 < HD) {
            av = *(const float4*)(Ap + k0 + 8);
            bv = *(const float4*)(Wp + k0 + 8);
        }

        wmma::fragment<wmma::matrix_a, 16, 16, 8, wmma::precision::tf32, wmma::row_major> ah[4], al[4];
#pragma unroll
        for (int i = 0; i < 4; i++) {
            wmma::load_matrix_sync(ah[i], &As_hi[wm * 64 + i * 16][0], 8);
            wmma::load_matrix_sync(al[i], &As_lo[wm * 64 + i * 16][0], 8);
        }
#pragma unroll
        for (int j = 0; j < 2; j++) {
            wmma::fragment<wmma::matrix_b, 16, 16, 8, wmma::precision::tf32, wmma::col_major> bhf, blf;
            wmma::load_matrix_sync(bhf, &Bs_hi[wn * 32 + j * 16][0], 8);
            wmma::load_matrix_sync(blf, &Bs_lo[wn * 32 + j * 16][0], 8);
#pragma unroll
            for (int i = 0; i < 4; i++) {
                wmma::mma_sync(acc[i][j], ah[i], bhf, acc[i][j]);
                wmma::mma_sync(acc[i][j], ah[i], blf, acc[i][j]);
                wmma::mma_sync(acc[i][j], al[i], bhf, acc[i][j]);
            }
        }
    }

    // epilogue: stage each 16x16 tile through per-warp scratch, add bias, STG
#pragma unroll
    for (int i = 0; i < 4; i++) {
#pragma unroll
        for (int j = 0; j < 2; j++) {
            wmma::store_matrix_sync(&scr[wid][0][0], acc[i][j], 24, wmma::mem_row_major);
            __syncwarp();
#pragma unroll
            for (int q = 0; q < 2; q++) {
                const int e = lane + q * 32;            // 0..63
                const int r = e >> 2, cs = (e & 3) * 4;
                float4 v = *(const float4*)&scr[wid][r][cs];
                const int n = wn * 32 + j * 16 + cs;
                v.x += bb[n]; v.y += bb[n + 1]; v.z += bb[n + 2]; v.w += bb[n + 3];
                *(float4*)&Z[(size_t)(m0 + wm * 64 + i * 16 + r) * G4 + n0 + n] = v;
            }
            __syncwarp();
        }
    }
}

// ---------------- recurrent persistent kernel (R2-EXACT, frozen) -------------
__global__ __launch_bounds__(256, 1) void k_rec(const float* __restrict__ Whh,  // (G4, HD)
                                                const float* __restrict__ c0l,  // (HD)
                                                const float* __restrict__ Zin,  // (SEQ, G4)
                                                float* __restrict__ Xout,       // (SEQ, HD)
                                                unsigned base) {
    __shared__ float sh[2][HD];
    const int tid = threadIdx.x;
    const int w = tid >> 5, lane = tid & 31;
    const int u = blockIdx.x * 8 + w;

    unsigned sb;
    asm("{ .reg .u64 t; cvta.to.shared.u64 t, %1; cvt.u32.u64 %0, t; }"
        : "=r"(sb) : "l"((void*)sh));
    sb += (unsigned)lane * 8u;

    unsigned long long wp[4][16];
#pragma unroll
    for (int g = 0; g < 4; g++) {
        const float* rp = Whh + (size_t)(g * HD + u) * HD + 2 * lane;
#pragma unroll
        for (int j = 0; j < 16; j++) {
            const float2 v = *(const float2*)(rp + 64 * j);
            asm("mov.b64 %0, {%1, %2};" : "=l"(wp[g][j]) : "f"(v.x), "f"(v.y));
        }
    }
    float c = c0l[u];   // only lane 0's copy is used

#pragma unroll 1
    for (int t = 0; t < SEQ; t++) {
        float z0 = 0.f, z1 = 0.f, z2 = 0.f, z3 = 0.f;
        if (lane == 0) {
            const float* zp = Zin + (size_t)t * G4 + u;
            z0 = zp[0]; z1 = zp[HD]; z2 = zp[2 * HD]; z3 = zp[3 * HD];
        }
        const unsigned target = base + (unsigned)t;
        {
            const unsigned* fp = &g_flags[tid >> 1];
            while (ld_acq(fp) < target) {}
            const float4 v = __ldcg((const float4*)(g_h + ((t + 1) & 1) * HD) + tid);
            *(float4*)&sh[t & 1][tid * 4] = v;
        }
        __syncthreads();

        const unsigned sbase = sb + (unsigned)((t & 1) << 12);
        unsigned long long a0 = 0ull, a1 = 0ull, a2 = 0ull, a3 = 0ull;
#pragma unroll
        for (int j = 0; j < 16; j++) {
            unsigned long long hp;
            asm volatile("ld.shared.b64 %0, [%1];" : "=l"(hp) : "r"(sbase + (unsigned)(j * 256)));
            asm("fma.rn.f32x2 %0, %1, %2, %0;" : "+l"(a0) : "l"(wp[0][j]), "l"(hp));
            asm("fma.rn.f32x2 %0, %1, %2, %0;" : "+l"(a1) : "l"(wp[1][j]), "l"(hp));
            asm("fma.rn.f32x2 %0, %1, %2, %0;" : "+l"(a2) : "l"(wp[2][j]), "l"(hp));
            asm("fma.rn.f32x2 %0, %1, %2, %0;" : "+l"(a3) : "l"(wp[3][j]), "l"(hp));
        }
        float s0, s1, s2, s3;
        {
            float x, y;
            asm("mov.b64 {%0,%1}, %2;" : "=f"(x), "=f"(y) : "l"(a0)); s0 = x + y;
            asm("mov.b64 {%0,%1}, %2;" : "=f"(x), "=f"(y) : "l"(a1)); s1 = x + y;
            asm("mov.b64 {%0,%1}, %2;" : "=f"(x), "=f"(y) : "l"(a2)); s2 = x + y;
            asm("mov.b64 {%0,%1}, %2;" : "=f"(x), "=f"(y) : "l"(a3)); s3 = x + y;
        }
#pragma unroll
        for (int off = 16; off; off >>= 1) {
            s0 += __shfl_xor_sync(0xffffffffu, s0, off);
            s1 += __shfl_xor_sync(0xffffffffu, s1, off);
            s2 += __shfl_xor_sync(0xffffffffu, s2, off);
            s3 += __shfl_xor_sync(0xffffffffu, s3, off);
        }
        float h = 0.f;
        if (lane == 0) {
            const float ig = sigmf(s0 + z0);
            const float fg = sigmf(s1 + z1);
            const float gg = tanh_fast(s2 + z2);
            const float og = sigmf(s3 + z3);
            c = fg * c + ig * gg;
            h = og * tanh_fast(c);
            __stcg(&g_h[(t & 1) * HD + u], h);      // broadcast buffer (L2)
        }
        __syncthreads();                            // all h stores precede fence
        if (tid == 0) {
            __threadfence();                        // publish h (cumulative)
            st_relx(&g_flags[blockIdx.x], target + 1u);
        }
        if (lane == 0)
            Xout[(size_t)t * HD + u] = h;           // off the critical path
    }
}

// ---------------- final: tanh(leaky_relu(X) @ w2^T + b2) ---------------------
__global__ __launch_bounds__(256) void k_final(const float* __restrict__ Xin,
                                               const float* __restrict__ w2,   // (NIN, HD)
                                               const float* __restrict__ b2,
                                               float* __restrict__ y) {
    __shared__ float xs[64][65];
    __shared__ float ws[64][65];
    const int t0 = blockIdx.x * 64;
    const int tid = threadIdx.x;
    const int o = tid & 63, tq = tid >> 6;

    float acc[16];
#pragma unroll
    for (int i = 0; i < 16; i++) acc[i] = 0.0f;

    for (int k0 = 0; k0 < HD; k0 += 64) {
        __syncthreads();
        for (int i = tid; i < 64 * 64; i += 256) {
            const int r = i >> 6, cc = i & 63;
            float v = Xin[(size_t)(t0 + r) * HD + k0 + cc];
            xs[r][cc] = (v >= 0.0f) ? v : 0.01f * v;
            ws[r][cc] = w2[(size_t)r * HD + k0 + cc];
        }
        __syncthreads();
#pragma unroll 16
        for (int k = 0; k < 64; k++) {
            const float wv = ws[o][k];
#pragma unroll
            for (int i = 0; i < 16; i++) acc[i] = fmaf(xs[tq * 16 + i][k], wv, acc[i]);
        }
    }
    const float bb = b2[o];
#pragma unroll
    for (int i = 0; i < 16; i++)
        y[(size_t)(t0 + tq * 16 + i) * NIN + o] = tanh_fast(acc[i] + bb);
}

// ---------------- host launcher ----------------------------------------------
extern "C" void kernel_launch(void* const* d_in, const int* in_sizes, int n_in,
                              void* d_out, int out_size) {
    const float* data_in = (const float*)d_in[0];
    const float* w1      = (const float*)d_in[1];
    const float* b1      = (const float*)d_in[2];
    const float* W_ih    = (const float*)d_in[3];
    const float* W_hh    = (const float*)d_in[4];
    const float* b_ih    = (const float*)d_in[5];
    const float* b_hh    = (const float*)d_in[6];
    const float* w2      = (const float*)d_in[7];
    const float* b2      = (const float*)d_in[8];
    const float* h0      = (const float*)d_in[9];
    const float* c0      = (const float*)d_in[10];
    float* out = (float*)d_out;

    static float* dA = nullptr;
    static float* dB = nullptr;
    static float* dZ = nullptr;
    if (!dA) {   // host-side symbol queries; not allocations
        cudaGetSymbolAddress((void**)&dA, g_bufA);
        cudaGetSymbolAddress((void**)&dB, g_bufB);
        cudaGetSymbolAddress((void**)&dZ, g_Z);
    }
    float* bufs[2] = { dA, dB };

    k_init<<<4, 256>>>(h0);                                          // launch 1
    k_first<<<dim3(SEQ / 64, HD / 64), 256>>>(data_in, w1, b1, dA);  // launch 2
    k_nop<<<1, 32>>>();                                              // launch 3 (slot align)

    for (int l = 0; l < NLAYER; l++) {
        const float* Xin = bufs[l & 1];
        float* Xout = bufs[(l & 1) ^ 1];
        if (l > 0)
            k_prep<<<4, 256>>>(h0 + (size_t)l * HD);
        k_gemm<<<dim3(G4 / 128, SEQ / 128), 256>>>(Xin,              // launch 4 (l=0): profiled
                                                   W_ih + (size_t)l * G4 * HD,
                                                   b_ih + (size_t)l * G4,
                                                   b_hh + (size_t)l * G4,
                                                   dZ);
        k_rec<<<NCTA, 256>>>(W_hh + (size_t)l * G4 * HD,
                             c0 + (size_t)l * HD,
                             dZ,
                             Xout,
                             (unsigned)(l * SEQ));
    }
    k_final<<<SEQ / 64, 256>>>(bufs[NLAYER & 1], w2, b2, out);
}

// round 16
// speedup vs baseline: 1.6239x; 1.2121x over previous
#include <cuda_runtime.h>

#define SEQ   8192
#define HD    1024
#define G4    4096
#define NIN   64
#define NLAYER 5
#define NCTA  128
#define SENT  0x7FC0DEADu   // qNaN payload sentinel; real h is never NaN

// ---------------- scratch (device globals; no allocation allowed) ------------
__device__ float g_bufA[(size_t)(SEQ + 1) * HD];  // h-sequence ping (row0 = h_{-1})
__device__ float g_bufB[(size_t)(SEQ + 1) * HD];  // h-sequence pong
__device__ float g_Z[(size_t)SEQ * G4];           // input projections (with bias)

// ---------------- math helpers ----------------------------------------------
__device__ __forceinline__ float sigmf(float x) { return 1.0f / (1.0f + __expf(-x)); }
__device__ __forceinline__ float tanh_fast(float x) { return 1.0f - 2.0f / (__expf(2.0f * x) + 1.0f); }

__device__ __forceinline__ uint4 ld_vol4(const uint4* p) {
    uint4 v;
    asm volatile("ld.volatile.global.v4.b32 {%0,%1,%2,%3}, [%4];"
                 : "=r"(v.x), "=r"(v.y), "=r"(v.z), "=r"(v.w) : "l"(p) : "memory");
    return v;
}
__device__ __forceinline__ void st_vol4(float* p, float4 v) {
    asm volatile("st.volatile.global.v4.f32 [%0], {%1,%2,%3,%4};"
                 :: "l"(p), "f"(v.x), "f"(v.y), "f"(v.z), "f"(v.w) : "memory");
}

// ---------------- fill rows 1..SEQ of an h-sequence buffer with sentinel -----
__global__ void k_fill(float* __restrict__ X) {     // X points at row 1
    const uint4 s = make_uint4(SENT, SENT, SENT, SENT);
    uint4* p = (uint4*)X;
    const int n = SEQ * HD / 4;                     // 2M uint4
    for (int i = threadIdx.x + blockIdx.x * blockDim.x; i < n; i += blockDim.x * gridDim.x)
        p[i] = s;
}

// ---------------- prep: row 0 = h0[layer] -------------------------------------
__global__ void k_prep(float* __restrict__ X, const float* __restrict__ h0l) {
    const int i = threadIdx.x + blockIdx.x * blockDim.x;
    if (i < HD) X[i] = h0l[i];
}

// ---------------- first layer: leaky_relu(x @ w1^T + b1) ---------------------
__global__ __launch_bounds__(256) void k_first(const float* __restrict__ x,
                                               const float* __restrict__ w1,
                                               const float* __restrict__ b1,
                                               float* __restrict__ out) {   // rows 1..SEQ
    __shared__ float xs[64][NIN];
    __shared__ float ws[64][NIN + 1];
    const int t0 = blockIdx.x * 64;
    const int h0 = blockIdx.y * 64;
    const int tid = threadIdx.x;

    for (int i = tid; i < 64 * NIN; i += 256)
        xs[i >> 6][i & 63] = x[(size_t)(t0 + (i >> 6)) * NIN + (i & 63)];
    for (int i = tid; i < 64 * NIN; i += 256)
        ws[i >> 6][i & 63] = w1[(size_t)(h0 + (i >> 6)) * NIN + (i & 63)];
    __syncthreads();

    const int h = tid & 63, tq = tid >> 6;
    float acc[16];
#pragma unroll
    for (int i = 0; i < 16; i++) acc[i] = 0.0f;

#pragma unroll 16
    for (int k = 0; k < NIN; k++) {
        const float wv = ws[h][k];
#pragma unroll
        for (int i = 0; i < 16; i++) acc[i] = fmaf(xs[tq * 16 + i][k], wv, acc[i]);
    }
    const float bb = b1[h0 + h];
#pragma unroll
    for (int i = 0; i < 16; i++) {
        float v = acc[i] + bb;
        v = (v >= 0.0f) ? v : 0.01f * v;
        out[(size_t)(t0 + tq * 16 + i) * HD + h0 + h] = v;
    }
}

// ---------------- input-projection GEMM: Z = X @ Wih^T + (b_ih + b_hh) -------
// R2-exact SIMT SGEMM (wmma/3xTF32 measured slower on fallback HMMA).
__global__ __launch_bounds__(256, 2) void k_gemm(const float* __restrict__ A,   // (SEQ, HD)
                                                 const float* __restrict__ W,   // (G4, HD)
                                                 const float* __restrict__ bi,
                                                 const float* __restrict__ bh,
                                                 float* __restrict__ Z) {
    __shared__ float As[8][128];
    __shared__ float Bs[8][128];
    const int tid = threadIdx.x;
    const int tx = tid & 15, ty = tid >> 4;
    const int m0 = blockIdx.y * 128, n0 = blockIdx.x * 128;
    const int lr = tid >> 1, lk = (tid & 1) * 4;

    const float* Ap = A + (size_t)(m0 + lr) * HD + lk;
    const float* Wp = W + (size_t)(n0 + lr) * HD + lk;

    float acc[8][8];
#pragma unroll
    for (int i = 0; i < 8; i++)
#pragma unroll
        for (int j = 0; j < 8; j++) acc[i][j] = 0.0f;

    float4 av = *(const float4*)(Ap);
    float4 bv = *(const float4*)(Wp);

    for (int k0 = 0; k0 < HD; k0 += 8) {
        __syncthreads();
        As[lk + 0][lr] = av.x; As[lk + 1][lr] = av.y; As[lk + 2][lr] = av.z; As[lk + 3][lr] = av.w;
        Bs[lk + 0][lr] = bv.x; Bs[lk + 1][lr] = bv.y; Bs[lk + 2][lr] = bv.z; Bs[lk + 3][lr] = bv.w;
        __syncthreads();
        if (k0 + 8 < HD) {
            av = *(const float4*)(Ap + k0 + 8);
            bv = *(const float4*)(Wp + k0 + 8);
        }
#pragma unroll
        for (int kk = 0; kk < 8; kk++) {
            float ar[8], br[8];
            *(float4*)(ar)     = *(const float4*)&As[kk][ty * 8];
            *(float4*)(ar + 4) = *(const float4*)&As[kk][ty * 8 + 4];
            *(float4*)(br)     = *(const float4*)&Bs[kk][tx * 8];
            *(float4*)(br + 4) = *(const float4*)&Bs[kk][tx * 8 + 4];
#pragma unroll
            for (int i = 0; i < 8; i++)
#pragma unroll
                for (int j = 0; j < 8; j++) acc[i][j] = fmaf(ar[i], br[j], acc[i][j]);
        }
    }
    float bb[8];
#pragma unroll
    for (int j = 0; j < 8; j++) bb[j] = bi[n0 + tx * 8 + j] + bh[n0 + tx * 8 + j];
#pragma unroll
    for (int i = 0; i < 8; i++) {
        const size_t m = (size_t)(m0 + ty * 8 + i);
        float4 o0, o1;
        o0.x = acc[i][0] + bb[0]; o0.y = acc[i][1] + bb[1];
        o0.z = acc[i][2] + bb[2]; o0.w = acc[i][3] + bb[3];
        o1.x = acc[i][4] + bb[4]; o1.y = acc[i][5] + bb[5];
        o1.z = acc[i][6] + bb[6]; o1.w = acc[i][7] + bb[7];
        *(float4*)&Z[m * G4 + n0 + tx * 8]     = o0;
        *(float4*)&Z[m * G4 + n0 + tx * 8 + 4] = o1;
    }
}

// ---------------- recurrent persistent kernel: sentinel-sync -----------------
// The h-sequence buffer X (SEQ+1 rows) IS the sync medium: rows 1..SEQ are
// pre-filled with qNaN sentinel; producers publish 8 h values as two atomic
// 16B volatile stores; consumers poll their own 16B slice of row t directly.
// ONE L2 round trip replaces store->fence->flag->poll->load. Compute body is
// R2-exact (frozen).
__global__ __launch_bounds__(256, 1) void k_rec(const float* __restrict__ Whh,  // (G4, HD)
                                                const float* __restrict__ c0l,  // (HD)
                                                const float* __restrict__ Zin,  // (SEQ, G4)
                                                float* __restrict__ X) {        // (SEQ+1, HD)
    __shared__ float sh[2][HD];
    __shared__ float sh_h[8];
    const int tid = threadIdx.x;
    const int w = tid >> 5, lane = tid & 31;
    const int u = blockIdx.x * 8 + w;

    unsigned sb;
    asm("{ .reg .u64 t; cvta.to.shared.u64 t, %1; cvt.u32.u64 %0, t; }"
        : "=r"(sb) : "l"((void*)sh));
    sb += (unsigned)lane * 8u;

    // packed weight pairs: lane owns k in {64j+2*lane, 64j+2*lane+1}
    unsigned long long wp[4][16];
#pragma unroll
    for (int g = 0; g < 4; g++) {
        const float* rp = Whh + (size_t)(g * HD + u) * HD + 2 * lane;
#pragma unroll
        for (int j = 0; j < 16; j++) {
            const float2 v = *(const float2*)(rp + 64 * j);
            asm("mov.b64 %0, {%1, %2};" : "=l"(wp[g][j]) : "f"(v.x), "f"(v.y));
        }
    }
    float c = c0l[u];   // only lane 0's copy is used

#pragma unroll 1
    for (int t = 0; t < SEQ; t++) {
        // z prefetch (lane0 of each warp), issued before the wait (R2-exact)
        float z0 = 0.f, z1 = 0.f, z2 = 0.f, z3 = 0.f;
        if (lane == 0) {
            const float* zp = Zin + (size_t)t * G4 + u;
            z0 = zp[0]; z1 = zp[HD]; z2 = zp[2 * HD]; z3 = zp[3 * HD];
        }

        // poll own 16B slice of h_{t-1} (= row t) until no sentinel remains
        {
            const uint4* pp = (const uint4*)(X + (size_t)t * HD) + tid;
            uint4 v;
            do {
                v = ld_vol4(pp);
            } while (v.x == SENT || v.y == SENT || v.z == SENT || v.w == SENT);
            float4 hv;
            hv.x = __uint_as_float(v.x); hv.y = __uint_as_float(v.y);
            hv.z = __uint_as_float(v.z); hv.w = __uint_as_float(v.w);
            *(float4*)&sh[t & 1][tid * 4] = hv;
        }
        __syncthreads();                                      // bar1

        // packed dot: 64 x fma.rn.f32x2 + 16 x LDS.64 (R2-exact)
        const unsigned sbase = sb + (unsigned)((t & 1) << 12);
        unsigned long long a0 = 0ull, a1 = 0ull, a2 = 0ull, a3 = 0ull;
#pragma unroll
        for (int j = 0; j < 16; j++) {
            unsigned long long hp;
            asm volatile("ld.shared.b64 %0, [%1];" : "=l"(hp) : "r"(sbase + (unsigned)(j * 256)));
            asm("fma.rn.f32x2 %0, %1, %2, %0;" : "+l"(a0) : "l"(wp[0][j]), "l"(hp));
            asm("fma.rn.f32x2 %0, %1, %2, %0;" : "+l"(a1) : "l"(wp[1][j]), "l"(hp));
            asm("fma.rn.f32x2 %0, %1, %2, %0;" : "+l"(a2) : "l"(wp[2][j]), "l"(hp));
            asm("fma.rn.f32x2 %0, %1, %2, %0;" : "+l"(a3) : "l"(wp[3][j]), "l"(hp));
        }
        float s0, s1, s2, s3;
        {
            float x, y;
            asm("mov.b64 {%0,%1}, %2;" : "=f"(x), "=f"(y) : "l"(a0)); s0 = x + y;
            asm("mov.b64 {%0,%1}, %2;" : "=f"(x), "=f"(y) : "l"(a1)); s1 = x + y;
            asm("mov.b64 {%0,%1}, %2;" : "=f"(x), "=f"(y) : "l"(a2)); s2 = x + y;
            asm("mov.b64 {%0,%1}, %2;" : "=f"(x), "=f"(y) : "l"(a3)); s3 = x + y;
        }
#pragma unroll
        for (int off = 16; off; off >>= 1) {
            s0 += __shfl_xor_sync(0xffffffffu, s0, off);
            s1 += __shfl_xor_sync(0xffffffffu, s1, off);
            s2 += __shfl_xor_sync(0xffffffffu, s2, off);
            s3 += __shfl_xor_sync(0xffffffffu, s3, off);
        }
        if (lane == 0) {
            const float ig = sigmf(s0 + z0);
            const float fg = sigmf(s1 + z1);
            const float gg = tanh_fast(s2 + z2);
            const float og = sigmf(s3 + z3);
            c = fg * c + ig * gg;
            sh_h[w] = og * tanh_fast(c);                      // gather in SMEM
        }
        __syncthreads();                                      // bar2
        if (tid < 2) {
            // publish this CTA's 8 h values as two atomic 16B volatile stores
            const float4 o = *(const float4*)&sh_h[tid * 4];
            st_vol4(X + (size_t)(t + 1) * HD + blockIdx.x * 8 + tid * 4, o);
        }
    }
}

// ---------------- final: tanh(leaky_relu(X) @ w2^T + b2) ---------------------
__global__ __launch_bounds__(256) void k_final(const float* __restrict__ Xin,   // rows 1..SEQ
                                               const float* __restrict__ w2,    // (NIN, HD)
                                               const float* __restrict__ b2,
                                               float* __restrict__ y) {
    __shared__ float xs[64][65];
    __shared__ float ws[64][65];
    const int t0 = blockIdx.x * 64;
    const int tid = threadIdx.x;
    const int o = tid & 63, tq = tid >> 6;

    float acc[16];
#pragma unroll
    for (int i = 0; i < 16; i++) acc[i] = 0.0f;

    for (int k0 = 0; k0 < HD; k0 += 64) {
        __syncthreads();
        for (int i = tid; i < 64 * 64; i += 256) {
            const int r = i >> 6, cc = i & 63;
            float v = Xin[(size_t)(t0 + r) * HD + k0 + cc];
            xs[r][cc] = (v >= 0.0f) ? v : 0.01f * v;
            ws[r][cc] = w2[(size_t)r * HD + k0 + cc];
        }
        __syncthreads();
#pragma unroll 16
        for (int k = 0; k < 64; k++) {
            const float wv = ws[o][k];
#pragma unroll
            for (int i = 0; i < 16; i++) acc[i] = fmaf(xs[tq * 16 + i][k], wv, acc[i]);
        }
    }
    const float bb = b2[o];
#pragma unroll
    for (int i = 0; i < 16; i++)
        y[(size_t)(t0 + tq * 16 + i) * NIN + o] = tanh_fast(acc[i] + bb);
}

// ---------------- host launcher ----------------------------------------------
extern "C" void kernel_launch(void* const* d_in, const int* in_sizes, int n_in,
                              void* d_out, int out_size) {
    const float* data_in = (const float*)d_in[0];
    const float* w1      = (const float*)d_in[1];
    const float* b1      = (const float*)d_in[2];
    const float* W_ih    = (const float*)d_in[3];
    const float* W_hh    = (const float*)d_in[4];
    const float* b_ih    = (const float*)d_in[5];
    const float* b_hh    = (const float*)d_in[6];
    const float* w2      = (const float*)d_in[7];
    const float* b2      = (const float*)d_in[8];
    const float* h0      = (const float*)d_in[9];
    const float* c0      = (const float*)d_in[10];
    float* out = (float*)d_out;

    static float* dA = nullptr;
    static float* dB = nullptr;
    static float* dZ = nullptr;
    if (!dA) {   // host-side symbol queries; not allocations
        cudaGetSymbolAddress((void**)&dA, g_bufA);
        cudaGetSymbolAddress((void**)&dB, g_bufB);
        cudaGetSymbolAddress((void**)&dZ, g_Z);   // R15 bug: passed raw symbol before
    }
    float* bufs[2] = { dA, dB };

    k_first<<<dim3(SEQ / 64, HD / 64), 256>>>(data_in, w1, b1, dA + HD);  // rows 1..SEQ

    for (int l = 0; l < NLAYER; l++) {
        float* Xin = bufs[l & 1];
        float* Xout = bufs[(l & 1) ^ 1];
        k_fill<<<2048, 256>>>(Xout + HD);                 // sentinel rows 1..SEQ
        k_prep<<<4, 256>>>(Xout, h0 + (size_t)l * HD);    // row 0 = h_{-1}
        k_gemm<<<dim3(G4 / 128, SEQ / 128), 256>>>(Xin + HD,
                                                   W_ih + (size_t)l * G4 * HD,
                                                   b_ih + (size_t)l * G4,
                                                   b_hh + (size_t)l * G4,
                                                   dZ);
        k_rec<<<NCTA, 256>>>(W_hh + (size_t)l * G4 * HD,
                             c0 + (size_t)l * HD,
                             dZ,
                             Xout);
    }
    k_final<<<SEQ / 64, 256>>>(bufs[NLAYER & 1] + HD, w2, b2, out);
}